// round 6
// baseline (speedup 1.0000x reference)
#include <cuda_runtime.h>
#include <cuda_bf16.h>

#define Nn 64
#define Cc 192
#define Hh 64
#define Ww 64
#define HW 4096
#define TOTAL (Nn * Cc * HW)

// Scratch for depthwise output y (cudaMalloc forbidden -> static device array).
__device__ float g_y[TOTAL];
__device__ float g_mean[Cc];
__device__ float g_rstd[Cc];

// ---------------------------------------------------------------------------
// Kernel 1: ReLU + depthwise dilated 3x3 conv (dilation=2, pad=2, stride=1).
// One block per (n, c) plane; plane staged in smem with ReLU applied.
// ---------------------------------------------------------------------------
__global__ __launch_bounds__(256) void dw_kernel(const float* __restrict__ x,
                                                 const float* __restrict__ dw_w) {
    const int plane = blockIdx.x;      // n * Cc + c
    const int c = plane % Cc;
    const float* __restrict__ xp = x + (size_t)plane * HW;
    float* __restrict__ yp = g_y + (size_t)plane * HW;

    __shared__ float sm[HW];           // 16 KB

    float wv[9];
#pragma unroll
    for (int i = 0; i < 9; i++) wv[i] = dw_w[c * 9 + i];

    for (int i = threadIdx.x; i < HW; i += 256)
        sm[i] = fmaxf(xp[i], 0.0f);
    __syncthreads();

    for (int i = threadIdx.x; i < HW; i += 256) {
        const int h = i >> 6;
        const int w = i & 63;
        float acc = 0.0f;
#pragma unroll
        for (int kh = 0; kh < 3; kh++) {
            const int ih = h + 2 * (kh - 1);
            if ((unsigned)ih < 64u) {
#pragma unroll
                for (int kw = 0; kw < 3; kw++) {
                    const int iw = w + 2 * (kw - 1);
                    if ((unsigned)iw < 64u)
                        acc = fmaf(wv[kh * 3 + kw], sm[(ih << 6) + iw], acc);
                }
            }
        }
        yp[i] = acc;
    }
}

// ---------------------------------------------------------------------------
// Kernel 2: pointwise 1x1 conv as batched SGEMM.
// Per image n: Z(192 x 4096) = W(192 x 192) * Y(192 x 4096).
// BM=64 (out ch), BN=128 (pixels), BK=16, 256 threads, 8x4 microtile.
// ---------------------------------------------------------------------------
#define BM 64
#define BNP 128
#define BK 16
#define AST 68   // padded stride for transposed-A smem (mult of 4 for float4)

__global__ __launch_bounds__(256) void pw_gemm_kernel(const float* __restrict__ pw,
                                                      float* __restrict__ zout) {
    const int n = blockIdx.z;
    const int m_block = blockIdx.y * BM;
    const int p_block = blockIdx.x * BNP;
    const float* __restrict__ B = g_y + (size_t)n * Cc * HW;
    float* __restrict__ Z = zout + (size_t)n * Cc * HW;

    __shared__ float Ast[BK][AST];    // A transposed: [k][m]
    __shared__ float Bs[BK][BNP];

    const int tid = threadIdx.x;
    const int tx = tid & 31;          // pixel group
    const int ty = tid >> 5;          // warp id -> m group
    const int m0 = ty * 8;
    const int p0 = tx * 4;

    float acc[8][4];
#pragma unroll
    for (int i = 0; i < 8; i++)
#pragma unroll
        for (int j = 0; j < 4; j++) acc[i][j] = 0.0f;

    const int a_row = tid >> 2;           // 0..63
    const int a_col = (tid & 3) * 4;      // 0,4,8,12

    for (int kb = 0; kb < Cc; kb += BK) {
        // A chunk: 64 rows x 16 cols of pw, stored transposed
        float4 av = *(const float4*)(pw + (m_block + a_row) * Cc + kb + a_col);
        Ast[a_col + 0][a_row] = av.x;
        Ast[a_col + 1][a_row] = av.y;
        Ast[a_col + 2][a_row] = av.z;
        Ast[a_col + 3][a_row] = av.w;
        // B chunk: 16 rows x 128 cols (512 float4, 2 per thread)
#pragma unroll
        for (int l = 0; l < 2; l++) {
            const int idx = tid + l * 256;
            const int br = idx >> 5;
            const int bc = (idx & 31) * 4;
            float4 bv = *(const float4*)(B + (size_t)(kb + br) * HW + p_block + bc);
            *(float4*)(&Bs[br][bc]) = bv;
        }
        __syncthreads();
#pragma unroll
        for (int k = 0; k < BK; k++) {
            const float4 a0 = *(const float4*)(&Ast[k][m0]);
            const float4 a1 = *(const float4*)(&Ast[k][m0 + 4]);
            const float4 bv = *(const float4*)(&Bs[k][p0]);
            const float am[8] = {a0.x, a0.y, a0.z, a0.w, a1.x, a1.y, a1.z, a1.w};
            const float bp[4] = {bv.x, bv.y, bv.z, bv.w};
#pragma unroll
            for (int i = 0; i < 8; i++)
#pragma unroll
                for (int j = 0; j < 4; j++)
                    acc[i][j] = fmaf(am[i], bp[j], acc[i][j]);
        }
        __syncthreads();
    }

#pragma unroll
    for (int i = 0; i < 8; i++) {
        float4 v = make_float4(acc[i][0], acc[i][1], acc[i][2], acc[i][3]);
        *(float4*)(Z + (size_t)(m_block + m0 + i) * HW + p_block + p0) = v;
    }
}

// ---------------------------------------------------------------------------
// Kernel 3: per-channel batch statistics (deterministic tree reduction).
// One block per channel; double accumulators for accuracy.
// ---------------------------------------------------------------------------
__global__ __launch_bounds__(256) void stats_kernel(const float* __restrict__ z) {
    const int c = blockIdx.x;
    const int tid = threadIdx.x;
    double s = 0.0, sq = 0.0;
    for (int n = 0; n < Nn; n++) {
        const float* __restrict__ p = z + (size_t)(n * Cc + c) * HW;
        for (int i = tid * 4; i < HW; i += 256 * 4) {
            float4 v = *(const float4*)(p + i);
            s += (double)v.x + (double)v.y + (double)v.z + (double)v.w;
            sq += (double)v.x * v.x + (double)v.y * v.y +
                  (double)v.z * v.z + (double)v.w * v.w;
        }
    }
    __shared__ double ss[256];
    __shared__ double ssq[256];
    ss[tid] = s;
    ssq[tid] = sq;
    __syncthreads();
    for (int stride = 128; stride > 0; stride >>= 1) {
        if (tid < stride) {
            ss[tid] += ss[tid + stride];
            ssq[tid] += ssq[tid + stride];
        }
        __syncthreads();
    }
    if (tid == 0) {
        const double inv_n = 1.0 / (double)(Nn * HW);
        const double mean = ss[0] * inv_n;
        const double var = ssq[0] * inv_n - mean * mean;
        g_mean[c] = (float)mean;
        g_rstd[c] = (float)(1.0 / sqrt(var + 1e-5));
    }
}

// ---------------------------------------------------------------------------
// Kernel 4: in-place BN normalize + affine.
// ---------------------------------------------------------------------------
__global__ __launch_bounds__(256) void bn_kernel(float* __restrict__ z,
                                                 const float* __restrict__ gamma,
                                                 const float* __restrict__ beta) {
    const size_t f4 = (size_t)blockIdx.x * 256 + threadIdx.x;
    const size_t i = f4 * 4;
    if (i >= (size_t)TOTAL) return;
    const int c = (int)((i / HW) % Cc);
    const float m = g_mean[c];
    const float r = g_rstd[c];
    const float g = gamma[c] * r;
    const float b = beta[c] - m * g;
    float4 v = *(float4*)(z + i);
    v.x = fmaf(v.x, g, b);
    v.y = fmaf(v.y, g, b);
    v.z = fmaf(v.z, g, b);
    v.w = fmaf(v.w, g, b);
    *(float4*)(z + i) = v;
}

// ---------------------------------------------------------------------------
extern "C" void kernel_launch(void* const* d_in, const int* in_sizes, int n_in,
                              void* d_out, int out_size) {
    const float* x     = (const float*)d_in[0];   // (64,192,64,64)
    const float* dw_w  = (const float*)d_in[1];   // (192,1,3,3)
    const float* pw_w  = (const float*)d_in[2];   // (192,192)
    const float* gamma = (const float*)d_in[3];   // (192,)
    const float* beta  = (const float*)d_in[4];   // (192,)
    float* out = (float*)d_out;

    // 1) ReLU + depthwise dilated conv -> g_y
    dw_kernel<<<Nn * Cc, 256>>>(x, dw_w);

    // 2) Pointwise 1x1 as batched SGEMM -> d_out (holds z)
    dim3 grid(HW / BNP, Cc / BM, Nn);
    pw_gemm_kernel<<<grid, 256>>>(pw_w, out);

    // 3) Batch statistics per channel
    stats_kernel<<<Cc, 256>>>(out);

    // 4) Normalize in place
    bn_kernel<<<(TOTAL / 4 + 255) / 256, 256>>>(out, gamma, beta);
}

// round 7
// speedup vs baseline: 1.5093x; 1.5093x over previous
#include <cuda_runtime.h>
#include <cuda_bf16.h>
#include <cstdint>

#define Nn 64
#define Cc 192
#define Hh 64
#define Ww 64
#define HW 4096
#define TOTAL (Nn * Cc * HW)

// Scratch (cudaMalloc forbidden -> static device arrays).
__device__ float  g_y[TOTAL];
__device__ float  g_mean[Cc];
__device__ float  g_rstd[Cc];
__device__ double g_psum[Cc * 8];
__device__ double g_psumsq[Cc * 8];

// ---------------------------------------------------------------------------
// Kernel 1: ReLU + depthwise dilated 3x3 conv (dilation=2, pad=2, stride=1).
// ---------------------------------------------------------------------------
__global__ __launch_bounds__(256) void dw_kernel(const float* __restrict__ x,
                                                 const float* __restrict__ dw_w) {
    const int plane = blockIdx.x;      // n * Cc + c
    const int c = plane % Cc;
    const float* __restrict__ xp = x + (size_t)plane * HW;
    float* __restrict__ yp = g_y + (size_t)plane * HW;

    __shared__ float sm[HW];           // 16 KB

    float wv[9];
#pragma unroll
    for (int i = 0; i < 9; i++) wv[i] = dw_w[c * 9 + i];

    for (int i = threadIdx.x; i < HW; i += 256)
        sm[i] = fmaxf(xp[i], 0.0f);
    __syncthreads();

    for (int i = threadIdx.x; i < HW; i += 256) {
        const int h = i >> 6;
        const int w = i & 63;
        float acc = 0.0f;
#pragma unroll
        for (int kh = 0; kh < 3; kh++) {
            const int ih = h + 2 * (kh - 1);
            if ((unsigned)ih < 64u) {
#pragma unroll
                for (int kw = 0; kw < 3; kw++) {
                    const int iw = w + 2 * (kw - 1);
                    if ((unsigned)iw < 64u)
                        acc = fmaf(wv[kh * 3 + kw], sm[(ih << 6) + iw], acc);
                }
            }
        }
        yp[i] = acc;
    }
}

// ---------------------------------------------------------------------------
// Kernel 2: pointwise 1x1 conv as batched GEMM on TENSOR CORES (TF32 mma.sync).
// Per image n: Z(192 x 4096) = W(192 x 192) * Y(192 x 4096).
// Block tile: M=64 (out ch) x N=128 (pixels), K-chunks of 32.
// 8 warps as 2(m) x 4(n); warp tile 32x32 = 2x4 mma(m16n8k8) per k-step.
// ---------------------------------------------------------------------------
#define GBM 64
#define GBN 128
#define GBK 32
#define AS_STRIDE 36    // 36 % 32 == 4 -> frag reads (g*4+t) conflict-free
#define BS_STRIDE 136   // 136 % 32 == 8 -> frag reads (t*8+g) conflict-free

__device__ __forceinline__ uint32_t f2tf(float f) {
    uint32_t r;
    asm("cvt.rna.tf32.f32 %0, %1;" : "=r"(r) : "f"(f));
    return r;
}

__device__ __forceinline__ void mma_tf32(float& c0, float& c1, float& c2, float& c3,
                                         uint32_t a0, uint32_t a1, uint32_t a2, uint32_t a3,
                                         uint32_t b0, uint32_t b1) {
    asm volatile(
        "mma.sync.aligned.m16n8k8.row.col.f32.tf32.tf32.f32 "
        "{%0,%1,%2,%3}, {%4,%5,%6,%7}, {%8,%9}, {%0,%1,%2,%3};"
        : "+f"(c0), "+f"(c1), "+f"(c2), "+f"(c3)
        : "r"(a0), "r"(a1), "r"(a2), "r"(a3), "r"(b0), "r"(b1));
}

__global__ __launch_bounds__(256) void pw_mma_kernel(const float* __restrict__ pw,
                                                     float* __restrict__ zout) {
    const int n = blockIdx.z;
    const int m_block = blockIdx.y * GBM;
    const int p_block = blockIdx.x * GBN;
    const float* __restrict__ B = g_y + (size_t)n * Cc * HW;
    float* __restrict__ Z = zout + (size_t)n * Cc * HW;

    __shared__ uint32_t As[GBM][AS_STRIDE];   // [m][k] tf32 bits, ~9.2 KB
    __shared__ uint32_t Bs[GBK][BS_STRIDE];   // [k][n] tf32 bits, ~17.4 KB

    const int tid = threadIdx.x;
    const int wid = tid >> 5;
    const int lane = tid & 31;
    const int g = lane >> 2;     // group id (0..7)
    const int t = lane & 3;      // thread-in-group (0..3)
    const int warp_m = (wid >> 2) * 32;   // 0 or 32
    const int warp_n = (wid & 3) * 32;    // 0,32,64,96

    float acc[2][4][4];
#pragma unroll
    for (int i = 0; i < 2; i++)
#pragma unroll
        for (int j = 0; j < 4; j++)
#pragma unroll
            for (int q = 0; q < 4; q++) acc[i][j][q] = 0.0f;

    for (int kb = 0; kb < Cc; kb += GBK) {
        // --- Load A chunk: 64 rows x 32 cols of pw; cvt to tf32 in smem ---
#pragma unroll
        for (int l = 0; l < 2; l++) {
            const int idx = tid + l * 256;          // 0..511
            const int row = idx >> 3;               // 0..63
            const int col4 = (idx & 7) * 4;         // 0..28
            float4 v = *(const float4*)(pw + (m_block + row) * Cc + kb + col4);
            uint4 u = make_uint4(f2tf(v.x), f2tf(v.y), f2tf(v.z), f2tf(v.w));
            *(uint4*)(&As[row][col4]) = u;
        }
        // --- Load B chunk: 32 rows x 128 cols of y; cvt to tf32 in smem ---
#pragma unroll
        for (int l = 0; l < 4; l++) {
            const int idx = tid + l * 256;          // 0..1023
            const int row = idx >> 5;               // 0..31
            const int col4 = (idx & 31) * 4;        // 0..124
            float4 v = *(const float4*)(B + (size_t)(kb + row) * HW + p_block + col4);
            uint4 u = make_uint4(f2tf(v.x), f2tf(v.y), f2tf(v.z), f2tf(v.w));
            *(uint4*)(&Bs[row][col4]) = u;
        }
        __syncthreads();

#pragma unroll
        for (int ks = 0; ks < GBK; ks += 8) {
            uint32_t a[2][4], b[4][2];
#pragma unroll
            for (int mt = 0; mt < 2; mt++) {
                const int mr = warp_m + mt * 16 + g;
                a[mt][0] = As[mr][ks + t];
                a[mt][1] = As[mr + 8][ks + t];
                a[mt][2] = As[mr][ks + t + 4];
                a[mt][3] = As[mr + 8][ks + t + 4];
            }
#pragma unroll
            for (int nt = 0; nt < 4; nt++) {
                const int nc = warp_n + nt * 8 + g;
                b[nt][0] = Bs[ks + t][nc];
                b[nt][1] = Bs[ks + t + 4][nc];
            }
#pragma unroll
            for (int mt = 0; mt < 2; mt++)
#pragma unroll
                for (int nt = 0; nt < 4; nt++)
                    mma_tf32(acc[mt][nt][0], acc[mt][nt][1],
                             acc[mt][nt][2], acc[mt][nt][3],
                             a[mt][0], a[mt][1], a[mt][2], a[mt][3],
                             b[nt][0], b[nt][1]);
        }
        __syncthreads();
    }

    // --- Store: c0,c1 at (row, 2t/2t+1); c2,c3 at (row+8, ...) ---
#pragma unroll
    for (int mt = 0; mt < 2; mt++) {
        const int r0 = m_block + warp_m + mt * 16 + g;
#pragma unroll
        for (int nt = 0; nt < 4; nt++) {
            const int col = p_block + warp_n + nt * 8 + 2 * t;
            float2 v0 = make_float2(acc[mt][nt][0], acc[mt][nt][1]);
            float2 v1 = make_float2(acc[mt][nt][2], acc[mt][nt][3]);
            *(float2*)(Z + (size_t)r0 * HW + col) = v0;
            *(float2*)(Z + (size_t)(r0 + 8) * HW + col) = v1;
        }
    }
}

// ---------------------------------------------------------------------------
// Kernel 3a: per-channel partial statistics (192 x 8 blocks, deterministic).
// ---------------------------------------------------------------------------
__global__ __launch_bounds__(256) void stats1_kernel(const float* __restrict__ z) {
    const int c = blockIdx.x;
    const int part = blockIdx.y;           // 0..7, 8 images each
    const int tid = threadIdx.x;
    double s = 0.0, sq = 0.0;
    for (int nl = 0; nl < 8; nl++) {
        const int n = part * 8 + nl;
        const float* __restrict__ p = z + (size_t)(n * Cc + c) * HW;
        for (int i = tid * 4; i < HW; i += 256 * 4) {
            float4 v = *(const float4*)(p + i);
            s += (double)v.x + (double)v.y + (double)v.z + (double)v.w;
            sq += (double)v.x * v.x + (double)v.y * v.y +
                  (double)v.z * v.z + (double)v.w * v.w;
        }
    }
    __shared__ double ss[256];
    __shared__ double ssq[256];
    ss[tid] = s;
    ssq[tid] = sq;
    __syncthreads();
    for (int stride = 128; stride > 0; stride >>= 1) {
        if (tid < stride) {
            ss[tid] += ss[tid + stride];
            ssq[tid] += ssq[tid + stride];
        }
        __syncthreads();
    }
    if (tid == 0) {
        g_psum[c * 8 + part] = ss[0];
        g_psumsq[c * 8 + part] = ssq[0];
    }
}

// Kernel 3b: finalize mean/rstd per channel.
__global__ __launch_bounds__(192) void stats2_kernel() {
    const int c = threadIdx.x;
    double s = 0.0, sq = 0.0;
#pragma unroll
    for (int p = 0; p < 8; p++) {
        s += g_psum[c * 8 + p];
        sq += g_psumsq[c * 8 + p];
    }
    const double inv_n = 1.0 / (double)(Nn * HW);
    const double mean = s * inv_n;
    const double var = sq * inv_n - mean * mean;
    g_mean[c] = (float)mean;
    g_rstd[c] = (float)(1.0 / sqrt(var + 1e-5));
}

// ---------------------------------------------------------------------------
// Kernel 4: in-place BN normalize + affine.
// ---------------------------------------------------------------------------
__global__ __launch_bounds__(256) void bn_kernel(float* __restrict__ z,
                                                 const float* __restrict__ gamma,
                                                 const float* __restrict__ beta) {
    const size_t f4 = (size_t)blockIdx.x * 256 + threadIdx.x;
    const size_t i = f4 * 4;
    if (i >= (size_t)TOTAL) return;
    const int c = (int)((i / HW) % Cc);
    const float m = g_mean[c];
    const float r = g_rstd[c];
    const float gg = gamma[c] * r;
    const float b = beta[c] - m * gg;
    float4 v = *(float4*)(z + i);
    v.x = fmaf(v.x, gg, b);
    v.y = fmaf(v.y, gg, b);
    v.z = fmaf(v.z, gg, b);
    v.w = fmaf(v.w, gg, b);
    *(float4*)(z + i) = v;
}

// ---------------------------------------------------------------------------
extern "C" void kernel_launch(void* const* d_in, const int* in_sizes, int n_in,
                              void* d_out, int out_size) {
    const float* x     = (const float*)d_in[0];   // (64,192,64,64)
    const float* dw_w  = (const float*)d_in[1];   // (192,1,3,3)
    const float* pw_w  = (const float*)d_in[2];   // (192,192)
    const float* gamma = (const float*)d_in[3];   // (192,)
    const float* beta  = (const float*)d_in[4];   // (192,)
    float* out = (float*)d_out;

    // 1) ReLU + depthwise dilated conv -> g_y
    dw_kernel<<<Nn * Cc, 256>>>(x, dw_w);

    // 2) Pointwise 1x1 as batched TF32 tensor-core GEMM -> d_out (holds z)
    dim3 grid(HW / GBN, Cc / GBM, Nn);
    pw_mma_kernel<<<grid, 256>>>(pw_w, out);

    // 3) Batch statistics per channel (two-stage, deterministic)
    stats1_kernel<<<dim3(Cc, 8), 256>>>(out);
    stats2_kernel<<<1, Cc>>>();

    // 4) Normalize in place
    bn_kernel<<<(TOTAL / 4 + 255) / 256, 256>>>(out, gamma, beta);
}

// round 13
// speedup vs baseline: 2.7317x; 1.8100x over previous
#include <cuda_runtime.h>
#include <cuda_bf16.h>
#include <cstdint>

#define Nn 64
#define Cc 192
#define HW 4096
#define TOTAL (Nn * Cc * HW)
#define NPB 2048                 // pw blocks: 32 pixel tiles * 64 images

// Scratch (cudaMalloc forbidden -> static device arrays).
__device__ float g_y[TOTAL];           // dw output, pre-rounded to tf32
__device__ float g_pw_tf[Cc * Cc];     // pw weights, pre-rounded to tf32
__device__ float g_pb[Cc * NPB];       // per-block per-channel partial sums
__device__ float g_pbq[Cc * NPB];      // per-block per-channel partial sumsq
__device__ float g_mean[Cc];
__device__ float g_rstd[Cc];

// ===========================================================================
// Helpers
// ===========================================================================
__device__ __forceinline__ uint32_t f2tf(float f) {
    uint32_t r;
    asm("cvt.rna.tf32.f32 %0, %1;" : "=r"(r) : "f"(f));
    return r;
}

__device__ __forceinline__ uint32_t smem_u32(const void* p) {
    uint32_t a;
    asm("{ .reg .u64 t; cvta.to.shared.u64 t, %1; cvt.u32.u64 %0, t; }"
        : "=r"(a) : "l"(p));
    return a;
}

#define CP_ASYNC16(dst, src) \
    asm volatile("cp.async.cg.shared.global [%0], [%1], 16;" \
                 :: "r"(dst), "l"(src) : "memory")
#define CP_COMMIT() asm volatile("cp.async.commit_group;" ::: "memory")
#define CP_WAIT(n)  asm volatile("cp.async.wait_group %0;" :: "n"(n) : "memory")

__device__ __forceinline__ void mma_tf32(float& c0, float& c1, float& c2, float& c3,
                                         uint32_t a0, uint32_t a1, uint32_t a2, uint32_t a3,
                                         uint32_t b0, uint32_t b1) {
    asm volatile(
        "mma.sync.aligned.m16n8k8.row.col.f32.tf32.tf32.f32 "
        "{%0,%1,%2,%3}, {%4,%5,%6,%7}, {%8,%9}, {%0,%1,%2,%3};"
        : "+f"(c0), "+f"(c1), "+f"(c2), "+f"(c3)
        : "r"(a0), "r"(a1), "r"(a2), "r"(a3), "r"(b0), "r"(b1));
}

// ---------------------------------------------------------------------------
// Kernel 0: pre-round pw weights to tf32 (rna).
// ---------------------------------------------------------------------------
__global__ __launch_bounds__(256) void pwround_kernel(const float* __restrict__ pw) {
    const int i = blockIdx.x * 256 + threadIdx.x;
    if (i < Cc * Cc) g_pw_tf[i] = __uint_as_float(f2tf(pw[i]));
}

// ---------------------------------------------------------------------------
// Kernel 1: ReLU + depthwise dilated 3x3 conv; output pre-rounded to tf32.
// ---------------------------------------------------------------------------
__global__ __launch_bounds__(256) void dw_kernel(const float* __restrict__ x,
                                                 const float* __restrict__ dw_w) {
    const int plane = blockIdx.x;      // n * Cc + c
    const int c = plane % Cc;
    const float* __restrict__ xp = x + (size_t)plane * HW;
    float* __restrict__ yp = g_y + (size_t)plane * HW;

    __shared__ float sm[HW];           // 16 KB

    float wv[9];
#pragma unroll
    for (int i = 0; i < 9; i++) wv[i] = dw_w[c * 9 + i];

    for (int i = threadIdx.x; i < HW; i += 256)
        sm[i] = fmaxf(xp[i], 0.0f);
    __syncthreads();

    for (int i = threadIdx.x; i < HW; i += 256) {
        const int h = i >> 6;
        const int w = i & 63;
        float acc = 0.0f;
#pragma unroll
        for (int kh = 0; kh < 3; kh++) {
            const int ih = h + 2 * (kh - 1);
            if ((unsigned)ih < 64u) {
#pragma unroll
                for (int kw = 0; kw < 3; kw++) {
                    const int iw = w + 2 * (kw - 1);
                    if ((unsigned)iw < 64u)
                        acc = fmaf(wv[kh * 3 + kw], sm[(ih << 6) + iw], acc);
                }
            }
        }
        yp[i] = __uint_as_float(f2tf(acc));   // pre-round for tf32 GEMM
    }
}

// ---------------------------------------------------------------------------
// Kernel 2: pointwise 1x1 conv as TF32 mma.sync GEMM + fused stats partials.
// Block tile: M=192 (ALL out channels) x N=128 pixels, K=192 in 6 chunks of 32.
// 512 threads = 16 warps as 4(m) x 4(n); warp tile 48x32 (3x4 m16n8k8).
// Weights (A) fully resident in smem; B (y) double-buffered via cp.async.
// ---------------------------------------------------------------------------
#define AS_W 196      // 196 % 32 == 4 -> a-frag banks (4g+t) all distinct
#define BS_W 136      // 136 % 32 == 8 -> b-frag banks (8t+g) all distinct
#define SM_A    0
#define SM_B0   (192 * AS_W * 4)                 // 150528
#define SM_B1   (SM_B0 + 32 * BS_W * 4)          // +17408
#define SM_SUM  (SM_B1 + 32 * BS_W * 4)          // 185344
#define SM_SUMQ (SM_SUM + 4 * Cc * 4)            // +3072
#define SM_TOT  (SM_SUMQ + 4 * Cc * 4)           // 191488 bytes

__global__ __launch_bounds__(512)
void pw_mma2_kernel(float* __restrict__ zout) {
    extern __shared__ char smem[];
    const uint32_t sb = smem_u32(smem);
    const int tid = threadIdx.x;
    const int wid = tid >> 5;
    const int lane = tid & 31;
    const int g = lane >> 2;          // 0..7
    const int t = lane & 3;           // 0..3
    const int warp_m = (wid >> 2) * 48;   // 0,48,96,144
    const int wn = wid & 3;
    const int warp_n = wn * 32;           // 0,32,64,96

    const int px = blockIdx.x;            // pixel tile (0..31)
    const int n = blockIdx.y;             // image
    const int p_block = px * 128;
    const int bid = n * 32 + px;          // 0..2047
    const float* __restrict__ Y = g_y + (size_t)n * Cc * HW;
    float* __restrict__ Z = zout + (size_t)n * Cc * HW;

    // ---- Prologue: cp.async full weight matrix A [192][192] (stride 196) ----
#pragma unroll
    for (int it = 0; it < 18; it++) {
        const int idx = tid + it * 512;          // 0..9215 float4s
        const int row = idx / 48;
        const int c4 = (idx % 48) * 4;
        CP_ASYNC16(sb + SM_A + (uint32_t)(row * AS_W + c4) * 4u,
                   g_pw_tf + row * Cc + c4);
    }
    // ---- B chunk 0 and 1 (each its own group) ----
#pragma unroll
    for (int it = 0; it < 2; it++) {
        const int idx = tid + it * 512;          // 0..1023
        const int row = idx >> 5;                // 0..31
        const int c4 = (idx & 31) * 4;
        CP_ASYNC16(sb + SM_B0 + (uint32_t)(row * BS_W + c4) * 4u,
                   Y + (size_t)row * HW + p_block + c4);
    }
    CP_COMMIT();   // group0: A + B0
#pragma unroll
    for (int it = 0; it < 2; it++) {
        const int idx = tid + it * 512;
        const int row = idx >> 5;
        const int c4 = (idx & 31) * 4;
        CP_ASYNC16(sb + SM_B1 + (uint32_t)(row * BS_W + c4) * 4u,
                   Y + (size_t)(32 + row) * HW + p_block + c4);
    }
    CP_COMMIT();   // group1: B1

    const float* As = (const float*)(smem + SM_A);

    float acc[3][4][4];
#pragma unroll
    for (int i = 0; i < 3; i++)
#pragma unroll
        for (int j = 0; j < 4; j++)
#pragma unroll
            for (int q = 0; q < 4; q++) acc[i][j][q] = 0.0f;

    for (int ch = 0; ch < 6; ch++) {
        if (ch < 5) { CP_WAIT(1); } else { CP_WAIT(0); }
        __syncthreads();

        const int kc = ch * 32;
        const float* Bs = (const float*)(smem + ((ch & 1) ? SM_B1 : SM_B0));

#pragma unroll
        for (int ks = 0; ks < 32; ks += 8) {
            uint32_t a[3][4], b[4][2];
            const int kcol = kc + ks + t;
#pragma unroll
            for (int mt = 0; mt < 3; mt++) {
                const int r0 = warp_m + mt * 16 + g;
                a[mt][0] = __float_as_uint(As[r0 * AS_W + kcol]);
                a[mt][1] = __float_as_uint(As[(r0 + 8) * AS_W + kcol]);
                a[mt][2] = __float_as_uint(As[r0 * AS_W + kcol + 4]);
                a[mt][3] = __float_as_uint(As[(r0 + 8) * AS_W + kcol + 4]);
            }
#pragma unroll
            for (int nt = 0; nt < 4; nt++) {
                const int nc = warp_n + nt * 8 + g;
                b[nt][0] = __float_as_uint(Bs[(ks + t) * BS_W + nc]);
                b[nt][1] = __float_as_uint(Bs[(ks + t + 4) * BS_W + nc]);
            }
#pragma unroll
            for (int mt = 0; mt < 3; mt++)
#pragma unroll
                for (int nt = 0; nt < 4; nt++)
                    mma_tf32(acc[mt][nt][0], acc[mt][nt][1],
                             acc[mt][nt][2], acc[mt][nt][3],
                             a[mt][0], a[mt][1], a[mt][2], a[mt][3],
                             b[nt][0], b[nt][1]);
        }
        __syncthreads();    // buffer (ch&1) free for refill

        if (ch + 2 < 6) {
            const int nk = ch + 2;
            const uint32_t boff = (nk & 1) ? SM_B1 : SM_B0;
#pragma unroll
            for (int it = 0; it < 2; it++) {
                const int idx = tid + it * 512;
                const int row = idx >> 5;
                const int c4 = (idx & 31) * 4;
                CP_ASYNC16(sb + boff + (uint32_t)(row * BS_W + c4) * 4u,
                           Y + (size_t)(nk * 32 + row) * HW + p_block + c4);
            }
            CP_COMMIT();
        }
    }

    // ---- Store z + accumulate per-channel partial sums over this tile ----
    float s[3][2], q[3][2];
#pragma unroll
    for (int mt = 0; mt < 3; mt++) { s[mt][0] = s[mt][1] = q[mt][0] = q[mt][1] = 0.0f; }

#pragma unroll
    for (int mt = 0; mt < 3; mt++) {
        const int r0 = warp_m + mt * 16 + g;
#pragma unroll
        for (int nt = 0; nt < 4; nt++) {
            const int col = p_block + warp_n + nt * 8 + 2 * t;
            const float c0 = acc[mt][nt][0], c1 = acc[mt][nt][1];
            const float c2 = acc[mt][nt][2], c3 = acc[mt][nt][3];
            *(float2*)(Z + (size_t)r0 * HW + col) = make_float2(c0, c1);
            *(float2*)(Z + (size_t)(r0 + 8) * HW + col) = make_float2(c2, c3);
            s[mt][0] += c0 + c1;           q[mt][0] += c0 * c0 + c1 * c1;
            s[mt][1] += c2 + c3;           q[mt][1] += c2 * c2 + c3 * c3;
        }
    }
    // reduce over the 4 lanes of each quad (fixed order -> deterministic)
#pragma unroll
    for (int off = 1; off < 4; off <<= 1) {
#pragma unroll
        for (int mt = 0; mt < 3; mt++) {
#pragma unroll
            for (int h = 0; h < 2; h++) {
                s[mt][h] += __shfl_xor_sync(0xffffffffu, s[mt][h], off);
                q[mt][h] += __shfl_xor_sync(0xffffffffu, q[mt][h], off);
            }
        }
    }
    float* sums = (float*)(smem + SM_SUM);     // [4][192]
    float* sumq = (float*)(smem + SM_SUMQ);    // [4][192]
    if (t == 0) {
#pragma unroll
        for (int mt = 0; mt < 3; mt++) {
            const int r0 = warp_m + mt * 16 + g;
            sums[wn * Cc + r0] = s[mt][0];
            sums[wn * Cc + r0 + 8] = s[mt][1];
            sumq[wn * Cc + r0] = q[mt][0];
            sumq[wn * Cc + r0 + 8] = q[mt][1];
        }
    }
    __syncthreads();
    if (tid < Cc) {
        float ts = 0.0f, tq = 0.0f;
#pragma unroll
        for (int w = 0; w < 4; w++) { ts += sums[w * Cc + tid]; tq += sumq[w * Cc + tid]; }
        g_pb[tid * NPB + bid] = ts;
        g_pbq[tid * NPB + bid] = tq;
    }
}

// ---------------------------------------------------------------------------
// Kernel 3: finalize stats — reduce 2048 partials per channel (deterministic).
// ---------------------------------------------------------------------------
__global__ __launch_bounds__(256) void stats2_kernel() {
    const int c = blockIdx.x;
    const int tid = threadIdx.x;
    double s = 0.0, sq = 0.0;
    for (int b = tid; b < NPB; b += 256) {
        s += (double)g_pb[c * NPB + b];
        sq += (double)g_pbq[c * NPB + b];
    }
    __shared__ double ss[256];
    __shared__ double ssq[256];
    ss[tid] = s;
    ssq[tid] = sq;
    __syncthreads();
    for (int stride = 128; stride > 0; stride >>= 1) {
        if (tid < stride) {
            ss[tid] += ss[tid + stride];
            ssq[tid] += ssq[tid + stride];
        }
        __syncthreads();
    }
    if (tid == 0) {
        const double inv_n = 1.0 / (double)(Nn * HW);
        const double mean = ss[0] * inv_n;
        const double var = ssq[0] * inv_n - mean * mean;
        g_mean[c] = (float)mean;
        g_rstd[c] = (float)(1.0 / sqrt(var + 1e-5));
    }
}

// ---------------------------------------------------------------------------
// Kernel 4: in-place BN normalize + affine.
// ---------------------------------------------------------------------------
__global__ __launch_bounds__(256) void bn_kernel(float* __restrict__ z,
                                                 const float* __restrict__ gamma,
                                                 const float* __restrict__ beta) {
    const size_t f4 = (size_t)blockIdx.x * 256 + threadIdx.x;
    const size_t i = f4 * 4;
    if (i >= (size_t)TOTAL) return;
    const int c = (int)((i / HW) % Cc);
    const float m = g_mean[c];
    const float r = g_rstd[c];
    const float gg = gamma[c] * r;
    const float b = beta[c] - m * gg;
    float4 v = *(float4*)(z + i);
    v.x = fmaf(v.x, gg, b);
    v.y = fmaf(v.y, gg, b);
    v.z = fmaf(v.z, gg, b);
    v.w = fmaf(v.w, gg, b);
    *(float4*)(z + i) = v;
}

// ---------------------------------------------------------------------------
extern "C" void kernel_launch(void* const* d_in, const int* in_sizes, int n_in,
                              void* d_out, int out_size) {
    const float* x     = (const float*)d_in[0];   // (64,192,64,64)
    const float* dw_w  = (const float*)d_in[1];   // (192,1,3,3)
    const float* pw_w  = (const float*)d_in[2];   // (192,192)
    const float* gamma = (const float*)d_in[3];   // (192,)
    const float* beta  = (const float*)d_in[4];   // (192,)
    float* out = (float*)d_out;

    // 0) Pre-round weights to tf32
    pwround_kernel<<<(Cc * Cc + 255) / 256, 256>>>(pw_w);

    // 1) ReLU + depthwise dilated conv -> g_y (tf32-rounded)
    dw_kernel<<<Nn * Cc, 256>>>(x, dw_w);

    // 2) Pointwise GEMM (tf32 mma.sync, cp.async pipeline) + stats partials
    cudaFuncSetAttribute(pw_mma2_kernel,
                         cudaFuncAttributeMaxDynamicSharedMemorySize, SM_TOT);
    dim3 grid(32, Nn);
    pw_mma2_kernel<<<grid, 512, SM_TOT>>>(out);

    // 3) Finalize batch statistics
    stats2_kernel<<<Cc, 256>>>();

    // 4) Normalize in place
    bn_kernel<<<(TOTAL / 4 + 255) / 256, 256>>>(out, gamma, beta);
}

// round 14
// speedup vs baseline: 3.2353x; 1.1843x over previous
#include <cuda_runtime.h>
#include <cuda_bf16.h>
#include <cstdint>

#define Nn 64
#define Cc 192
#define HW 4096
#define TOTAL (Nn * Cc * HW)
#define NPB 2048                 // pw blocks: 32 pixel tiles * 64 images

// Scratch (cudaMalloc forbidden -> static device arrays).
__device__ float g_y[TOTAL];           // dw output, pre-rounded to tf32
__device__ float g_pw_tf[Cc * Cc];     // pw weights, tf32 + k-pair interleaved
__device__ float g_pb[Cc * NPB];       // per-block per-channel partial sums
__device__ float g_pbq[Cc * NPB];      // per-block per-channel partial sumsq
__device__ float g_mean[Cc];
__device__ float g_rstd[Cc];

// ===========================================================================
// Helpers
// ===========================================================================
__device__ __forceinline__ uint32_t f2tf(float f) {
    uint32_t r;
    asm("cvt.rna.tf32.f32 %0, %1;" : "=r"(r) : "f"(f));
    return r;
}

__device__ __forceinline__ uint32_t smem_u32(const void* p) {
    uint32_t a;
    asm("{ .reg .u64 t; cvta.to.shared.u64 t, %1; cvt.u32.u64 %0, t; }"
        : "=r"(a) : "l"(p));
    return a;
}

#define CP_ASYNC16(dst, src) \
    asm volatile("cp.async.cg.shared.global [%0], [%1], 16;" \
                 :: "r"(dst), "l"(src) : "memory")
#define CP_COMMIT() asm volatile("cp.async.commit_group;" ::: "memory")
#define CP_WAIT(n)  asm volatile("cp.async.wait_group %0;" :: "n"(n) : "memory")

__device__ __forceinline__ void mma_tf32(float& c0, float& c1, float& c2, float& c3,
                                         uint32_t a0, uint32_t a1, uint32_t a2, uint32_t a3,
                                         uint32_t b0, uint32_t b1) {
    asm volatile(
        "mma.sync.aligned.m16n8k8.row.col.f32.tf32.tf32.f32 "
        "{%0,%1,%2,%3}, {%4,%5,%6,%7}, {%8,%9}, {%0,%1,%2,%3};"
        : "+f"(c0), "+f"(c1), "+f"(c2), "+f"(c3)
        : "r"(a0), "r"(a1), "r"(a2), "r"(a3), "r"(b0), "r"(b1));
}

// ---------------------------------------------------------------------------
// Kernel 0: pre-round pw weights to tf32 AND permute columns within each
// 8-group to [k0,k4,k1,k5,k2,k6,k3,k7] so (k, k+4) frag pairs are adjacent.
// ---------------------------------------------------------------------------
__global__ __launch_bounds__(256) void pwround_kernel(const float* __restrict__ pw) {
    const int i = blockIdx.x * 256 + threadIdx.x;
    if (i < Cc * Cc) {
        const int row = i / Cc;
        const int col = i % Cc;
        const int b = col & 7;
        const int nc = (col & ~7) | ((b & 3) * 2 + (b >> 2));
        g_pw_tf[row * Cc + nc] = __uint_as_float(f2tf(pw[i]));
    }
}

// ---------------------------------------------------------------------------
// Kernel 1: ReLU + depthwise dilated 3x3 conv; vectorized (4 outputs/thread,
// float4 LDS from a guard-padded smem plane). Output pre-rounded to tf32.
// Smem plane: [64][72] floats; cols 0..3 and 68..71 are zero guards, data at
// smem col = data col + 4 -> all boundary column taps read zeros.
// ---------------------------------------------------------------------------
__global__ __launch_bounds__(256) void dw_kernel(const float* __restrict__ x,
                                                 const float* __restrict__ dw_w) {
    const int plane = blockIdx.x;      // n * Cc + c
    const int c = plane % Cc;
    const float* __restrict__ xp = x + (size_t)plane * HW;
    float* __restrict__ yp = g_y + (size_t)plane * HW;

    __shared__ float sm[64][72];       // 18 KB
    const int tid = threadIdx.x;

    // Zero the column guards (2 float4 per row).
    for (int i = tid; i < 128; i += 256) {
        const int r = i >> 1;
        const int side = (i & 1) ? 68 : 0;
        *(float4*)&sm[r][side] = make_float4(0.f, 0.f, 0.f, 0.f);
    }
    // Stage plane with ReLU, float4 (1024 f4).
    for (int j = tid; j < 1024; j += 256) {
        float4 v = *(const float4*)(xp + j * 4);
        v.x = fmaxf(v.x, 0.f); v.y = fmaxf(v.y, 0.f);
        v.z = fmaxf(v.z, 0.f); v.w = fmaxf(v.w, 0.f);
        *(float4*)&sm[j >> 4][4 + ((j & 15) << 2)] = v;
    }
    __syncthreads();

    float wv[9];
#pragma unroll
    for (int i = 0; i < 9; i++) wv[i] = dw_w[c * 9 + i];

    // 1024 groups of 4 outputs; 4 groups per thread.
#pragma unroll
    for (int gi = 0; gi < 4; gi++) {
        const int g4 = tid + gi * 256;
        const int h = g4 >> 4;
        const int w0 = (g4 & 15) << 2;         // data col of first output
        float r0 = 0.f, r1 = 0.f, r2 = 0.f, r3 = 0.f;
#pragma unroll
        for (int kh = 0; kh < 3; kh++) {
            const int ih = h + 2 * kh - 2;
            if ((unsigned)ih < 64u) {
                // smem cols w0 .. w0+11 = data cols w0-4 .. w0+7
                const float4 A = *(const float4*)&sm[ih][w0];
                const float4 B = *(const float4*)&sm[ih][w0 + 4];
                const float4 C = *(const float4*)&sm[ih][w0 + 8];
                const float wa = wv[kh * 3 + 0];
                const float wb = wv[kh * 3 + 1];
                const float wc = wv[kh * 3 + 2];
                // output j taps data cols w0+j-2, w0+j, w0+j+2
                r0 = fmaf(wa, A.z, fmaf(wb, B.x, fmaf(wc, B.z, r0)));
                r1 = fmaf(wa, A.w, fmaf(wb, B.y, fmaf(wc, B.w, r1)));
                r2 = fmaf(wa, B.x, fmaf(wb, B.z, fmaf(wc, C.x, r2)));
                r3 = fmaf(wa, B.y, fmaf(wb, B.w, fmaf(wc, C.y, r3)));
            }
        }
        float4 o;
        o.x = __uint_as_float(f2tf(r0));
        o.y = __uint_as_float(f2tf(r1));
        o.z = __uint_as_float(f2tf(r2));
        o.w = __uint_as_float(f2tf(r3));
        *(float4*)(yp + h * 64 + w0) = o;
    }
}

// ---------------------------------------------------------------------------
// Kernel 2: pointwise 1x1 conv as TF32 mma.sync GEMM + fused stats partials.
// Block tile: M=192 (ALL out channels) x N=128 pixels, K=192 in 6 chunks of 32.
// 512 threads = 16 warps as 4(m) x 4(n); warp tile 48x32 (3x4 m16n8k8).
// Weights (A, k-pair interleaved) fully resident; B double-buffered cp.async.
// ---------------------------------------------------------------------------
#define AS_W 200      // AS_W/2 = 100 == 4 mod 16 -> float2 frag loads conflict-free
#define BS_W 136      // 136 % 32 == 8 -> b-frag banks (8t+g) distinct
#define SM_A    0
#define SM_B0   (192 * AS_W * 4)                 // 153600
#define SM_B1   (SM_B0 + 32 * BS_W * 4)          // +17408
#define SM_SUM  (SM_B1 + 32 * BS_W * 4)          // 188416
#define SM_SUMQ (SM_SUM + 4 * Cc * 4)            // +3072
#define SM_TOT  (SM_SUMQ + 4 * Cc * 4)           // 194560 bytes

__global__ __launch_bounds__(512)
void pw_mma2_kernel(float* __restrict__ zout) {
    extern __shared__ char smem[];
    const uint32_t sb = smem_u32(smem);
    const int tid = threadIdx.x;
    const int wid = tid >> 5;
    const int lane = tid & 31;
    const int g = lane >> 2;          // 0..7
    const int t = lane & 3;           // 0..3
    const int warp_m = (wid >> 2) * 48;   // 0,48,96,144
    const int wn = wid & 3;
    const int warp_n = wn * 32;           // 0,32,64,96

    const int px = blockIdx.x;            // pixel tile (0..31)
    const int n = blockIdx.y;             // image
    const int p_block = px * 128;
    const int bid = n * 32 + px;          // 0..2047
    const float* __restrict__ Y = g_y + (size_t)n * Cc * HW;
    float* __restrict__ Z = zout + (size_t)n * Cc * HW;

    // ---- Prologue: cp.async full weight matrix A [192][192] (stride 200) ----
#pragma unroll
    for (int it = 0; it < 18; it++) {
        const int idx = tid + it * 512;          // 0..9215 float4s
        const int row = idx / 48;
        const int c4 = (idx % 48) * 4;
        CP_ASYNC16(sb + SM_A + (uint32_t)(row * AS_W + c4) * 4u,
                   g_pw_tf + row * Cc + c4);
    }
    // ---- B chunk 0 and 1 (each its own group) ----
#pragma unroll
    for (int it = 0; it < 2; it++) {
        const int idx = tid + it * 512;          // 0..1023
        const int row = idx >> 5;                // 0..31
        const int c4 = (idx & 31) * 4;
        CP_ASYNC16(sb + SM_B0 + (uint32_t)(row * BS_W + c4) * 4u,
                   Y + (size_t)row * HW + p_block + c4);
    }
    CP_COMMIT();   // group0: A + B0
#pragma unroll
    for (int it = 0; it < 2; it++) {
        const int idx = tid + it * 512;
        const int row = idx >> 5;
        const int c4 = (idx & 31) * 4;
        CP_ASYNC16(sb + SM_B1 + (uint32_t)(row * BS_W + c4) * 4u,
                   Y + (size_t)(32 + row) * HW + p_block + c4);
    }
    CP_COMMIT();   // group1: B1

    const float* As = (const float*)(smem + SM_A);

    float acc[3][4][4];
#pragma unroll
    for (int i = 0; i < 3; i++)
#pragma unroll
        for (int j = 0; j < 4; j++)
#pragma unroll
            for (int q = 0; q < 4; q++) acc[i][j][q] = 0.0f;

    for (int ch = 0; ch < 6; ch++) {
        if (ch < 5) { CP_WAIT(1); } else { CP_WAIT(0); }
        __syncthreads();

        const int kc = ch * 32;
        const float* Bs = (const float*)(smem + ((ch & 1) ? SM_B1 : SM_B0));

#pragma unroll
        for (int ks = 0; ks < 32; ks += 8) {
            uint32_t a[3][4], b[4][2];
            const int kk = kc + ks;      // interleaved: (k=t, k=t+4) at kk+2t
#pragma unroll
            for (int mt = 0; mt < 3; mt++) {
                const int r0 = warp_m + mt * 16 + g;
                const float2 af0 = *(const float2*)&As[r0 * AS_W + kk + 2 * t];
                const float2 af1 = *(const float2*)&As[(r0 + 8) * AS_W + kk + 2 * t];
                a[mt][0] = __float_as_uint(af0.x);
                a[mt][1] = __float_as_uint(af1.x);
                a[mt][2] = __float_as_uint(af0.y);
                a[mt][3] = __float_as_uint(af1.y);
            }
#pragma unroll
            for (int nt = 0; nt < 4; nt++) {
                const int nc = warp_n + nt * 8 + g;
                b[nt][0] = __float_as_uint(Bs[(ks + t) * BS_W + nc]);
                b[nt][1] = __float_as_uint(Bs[(ks + t + 4) * BS_W + nc]);
            }
#pragma unroll
            for (int mt = 0; mt < 3; mt++)
#pragma unroll
                for (int nt = 0; nt < 4; nt++)
                    mma_tf32(acc[mt][nt][0], acc[mt][nt][1],
                             acc[mt][nt][2], acc[mt][nt][3],
                             a[mt][0], a[mt][1], a[mt][2], a[mt][3],
                             b[nt][0], b[nt][1]);
        }
        __syncthreads();    // buffer (ch&1) free for refill

        if (ch + 2 < 6) {
            const int nk = ch + 2;
            const uint32_t boff = (nk & 1) ? SM_B1 : SM_B0;
#pragma unroll
            for (int it = 0; it < 2; it++) {
                const int idx = tid + it * 512;
                const int row = idx >> 5;
                const int c4 = (idx & 31) * 4;
                CP_ASYNC16(sb + boff + (uint32_t)(row * BS_W + c4) * 4u,
                           Y + (size_t)(nk * 32 + row) * HW + p_block + c4);
            }
            CP_COMMIT();
        }
    }

    // ---- Store z + accumulate per-channel partial sums over this tile ----
    float s[3][2], q[3][2];
#pragma unroll
    for (int mt = 0; mt < 3; mt++) { s[mt][0] = s[mt][1] = q[mt][0] = q[mt][1] = 0.0f; }

#pragma unroll
    for (int mt = 0; mt < 3; mt++) {
        const int r0 = warp_m + mt * 16 + g;
#pragma unroll
        for (int nt = 0; nt < 4; nt++) {
            const int col = p_block + warp_n + nt * 8 + 2 * t;
            const float c0 = acc[mt][nt][0], c1 = acc[mt][nt][1];
            const float c2 = acc[mt][nt][2], c3 = acc[mt][nt][3];
            *(float2*)(Z + (size_t)r0 * HW + col) = make_float2(c0, c1);
            *(float2*)(Z + (size_t)(r0 + 8) * HW + col) = make_float2(c2, c3);
            s[mt][0] += c0 + c1;           q[mt][0] += c0 * c0 + c1 * c1;
            s[mt][1] += c2 + c3;           q[mt][1] += c2 * c2 + c3 * c3;
        }
    }
    // reduce over the 4 lanes of each quad (fixed order -> deterministic)
#pragma unroll
    for (int off = 1; off < 4; off <<= 1) {
#pragma unroll
        for (int mt = 0; mt < 3; mt++) {
#pragma unroll
            for (int h = 0; h < 2; h++) {
                s[mt][h] += __shfl_xor_sync(0xffffffffu, s[mt][h], off);
                q[mt][h] += __shfl_xor_sync(0xffffffffu, q[mt][h], off);
            }
        }
    }
    float* sums = (float*)(smem + SM_SUM);     // [4][192]
    float* sumq = (float*)(smem + SM_SUMQ);    // [4][192]
    if (t == 0) {
#pragma unroll
        for (int mt = 0; mt < 3; mt++) {
            const int r0 = warp_m + mt * 16 + g;
            sums[wn * Cc + r0] = s[mt][0];
            sums[wn * Cc + r0 + 8] = s[mt][1];
            sumq[wn * Cc + r0] = q[mt][0];
            sumq[wn * Cc + r0 + 8] = q[mt][1];
        }
    }
    __syncthreads();
    if (tid < Cc) {
        float ts = 0.0f, tq = 0.0f;
#pragma unroll
        for (int w = 0; w < 4; w++) { ts += sums[w * Cc + tid]; tq += sumq[w * Cc + tid]; }
        g_pb[tid * NPB + bid] = ts;
        g_pbq[tid * NPB + bid] = tq;
    }
}

// ---------------------------------------------------------------------------
// Kernel 3: finalize stats — reduce 2048 partials per channel (deterministic).
// ---------------------------------------------------------------------------
__global__ __launch_bounds__(256) void stats2_kernel() {
    const int c = blockIdx.x;
    const int tid = threadIdx.x;
    double s = 0.0, sq = 0.0;
    for (int b = tid; b < NPB; b += 256) {
        s += (double)g_pb[c * NPB + b];
        sq += (double)g_pbq[c * NPB + b];
    }
    __shared__ double ss[256];
    __shared__ double ssq[256];
    ss[tid] = s;
    ssq[tid] = sq;
    __syncthreads();
    for (int stride = 128; stride > 0; stride >>= 1) {
        if (tid < stride) {
            ss[tid] += ss[tid + stride];
            ssq[tid] += ssq[tid + stride];
        }
        __syncthreads();
    }
    if (tid == 0) {
        const double inv_n = 1.0 / (double)(Nn * HW);
        const double mean = ss[0] * inv_n;
        const double var = ssq[0] * inv_n - mean * mean;
        g_mean[c] = (float)mean;
        g_rstd[c] = (float)(1.0 / sqrt(var + 1e-5));
    }
}

// ---------------------------------------------------------------------------
// Kernel 4: in-place BN normalize + affine.
// ---------------------------------------------------------------------------
__global__ __launch_bounds__(256) void bn_kernel(float* __restrict__ z,
                                                 const float* __restrict__ gamma,
                                                 const float* __restrict__ beta) {
    const size_t f4 = (size_t)blockIdx.x * 256 + threadIdx.x;
    const size_t i = f4 * 4;
    if (i >= (size_t)TOTAL) return;
    const int c = (int)((i / HW) % Cc);
    const float m = g_mean[c];
    const float r = g_rstd[c];
    const float gg = gamma[c] * r;
    const float b = beta[c] - m * gg;
    float4 v = *(float4*)(z + i);
    v.x = fmaf(v.x, gg, b);
    v.y = fmaf(v.y, gg, b);
    v.z = fmaf(v.z, gg, b);
    v.w = fmaf(v.w, gg, b);
    *(float4*)(z + i) = v;
}

// ---------------------------------------------------------------------------
extern "C" void kernel_launch(void* const* d_in, const int* in_sizes, int n_in,
                              void* d_out, int out_size) {
    const float* x     = (const float*)d_in[0];   // (64,192,64,64)
    const float* dw_w  = (const float*)d_in[1];   // (192,1,3,3)
    const float* pw_w  = (const float*)d_in[2];   // (192,192)
    const float* gamma = (const float*)d_in[3];   // (192,)
    const float* beta  = (const float*)d_in[4];   // (192,)
    float* out = (float*)d_out;

    // 0) Pre-round + interleave weights to tf32
    pwround_kernel<<<(Cc * Cc + 255) / 256, 256>>>(pw_w);

    // 1) ReLU + depthwise dilated conv -> g_y (tf32-rounded)
    dw_kernel<<<Nn * Cc, 256>>>(x, dw_w);

    // 2) Pointwise GEMM (tf32 mma.sync, cp.async pipeline) + stats partials
    cudaFuncSetAttribute(pw_mma2_kernel,
                         cudaFuncAttributeMaxDynamicSharedMemorySize, SM_TOT);
    dim3 grid(32, Nn);
    pw_mma2_kernel<<<grid, 512, SM_TOT>>>(out);

    // 3) Finalize batch statistics
    stats2_kernel<<<Cc, 256>>>();

    // 4) Normalize in place
    bn_kernel<<<(TOTAL / 4 + 255) / 256, 256>>>(out, gamma, beta);
}